// round 1
// baseline (speedup 1.0000x reference)
#include <cuda_runtime.h>
#include <cstdint>

#define BATCHN 8
#define SEQN   4096
#define NPOS   (BATCHN*SEQN)
#define VOCABN 257
#define QD     256
#define DEPTHN 6
#define BSV    (NPOS*VOCABN)

typedef unsigned long long ull;

// ---------------- scratch (device globals; no allocations) ----------------
__device__ float4 g_wT[DEPTHN*QD*QD];   // [d][i][o] -> (wr,wi,wj,wk)  (6.3 MB)
__device__ float  g_wHT[1024*VOCABN];   // transposed head [k][j]      (1.05 MB)
__device__ float  g_qA[VOCABN*QD*4];    // q table ping                (1.05 MB)
__device__ float  g_qB[VOCABN*QD*4];    // q table pong
__device__ float  g_logits[VOCABN*VOCABN]; // per-token logits (264 KB)
__device__ float  g_L[VOCABN];          // per-token mean |q_r|

// ---------------- packed f32x2 helpers (Blackwell FFMA2) ----------------
__device__ __forceinline__ ull bcast2(float x) {
    unsigned int u = __float_as_uint(x);
    ull r;
    asm("mov.b64 %0, {%1, %2};" : "=l"(r) : "r"(u), "r"(u));
    return r;
}
__device__ __forceinline__ void fma2(ull& d, ull a, ull b) {
    asm("fma.rn.f32x2 %0, %1, %2, %0;" : "+l"(d) : "l"(a), "l"(b));
}
__device__ __forceinline__ float2 unpack2(ull v) {
    unsigned int lo, hi;
    asm("mov.b64 {%0, %1}, %2;" : "=r"(lo), "=r"(hi) : "l"(v));
    return make_float2(__uint_as_float(lo), __uint_as_float(hi));
}

// ---------------- K0: weight transposes ----------------
// blocks [0, DEPTHN*QD): transpose one (d,i) column of w_layers into g_wT
// blocks [DEPTHN*QD, +1024): transpose w_head column k into g_wHT
__global__ void k_prep(const float* __restrict__ wl, const float* __restrict__ wh) {
    int bid = blockIdx.x, tid = threadIdx.x;
    if (bid < DEPTHN * QD) {
        int d = bid >> 8, i = bid & 255, o = tid;
        const float* base = wl + (size_t)d * 4 * QD * QD;
        float wr = base[0 * QD * QD + o * QD + i];
        float wi = base[1 * QD * QD + o * QD + i];
        float wj = base[2 * QD * QD + o * QD + i];
        float wk = base[3 * QD * QD + o * QD + i];
        g_wT[(d * QD + i) * QD + o] = make_float4(wr, wi, wj, wk);
    } else {
        int k = bid - DEPTHN * QD;  // 0..1023
        for (int j = tid; j < VOCABN; j += 256)
            g_wHT[k * VOCABN + j] = wh[(size_t)j * 1024 + k];
    }
}

// ---------------- K1: expansion stages (cq 1 -> 256), one block per vocab token ----------------
__global__ void k_expand(const float* __restrict__ emb,
                         const float* __restrict__ e0, const float* __restrict__ e1,
                         const float* __restrict__ e2, const float* __restrict__ e3,
                         const float* __restrict__ e4, const float* __restrict__ e5,
                         const float* __restrict__ e6, const float* __restrict__ e7) {
    __shared__ float4 bufA[QD];
    __shared__ float4 bufB[QD];
    int v = blockIdx.x, tid = threadIdx.x;
    if (tid == 0)
        bufA[0] = make_float4(emb[v * 4 + 0], emb[v * 4 + 1], emb[v * 4 + 2], emb[v * 4 + 3]);
    __syncthreads();
    const float* ws[8] = {e0, e1, e2, e3, e4, e5, e6, e7};
    float4* cur = bufA;
    float4* nxt = bufB;
    for (int s = 0; s < 8; s++) {
        int cq = 1 << s;
        if (tid < cq) {
            const float* W = ws[s];
            int cq2 = cq * cq;
            float dr = 0.f, di = 0.f, dj = 0.f, dk = 0.f;
            for (int i = 0; i < cq; i++) {
                float4 q = cur[i];
                float wr = W[tid * cq + i];
                float wi = W[cq2 + tid * cq + i];
                float wj = W[2 * cq2 + tid * cq + i];
                float wk = W[3 * cq2 + tid * cq + i];
                dr += wr * q.x - wi * q.y - wj * q.z - wk * q.w;
                di += wi * q.x + wr * q.y + wk * q.z - wj * q.w;
                dj += wj * q.x - wk * q.y + wr * q.z + wi * q.w;
                dk += wk * q.x + wj * q.y - wi * q.z + wr * q.w;
            }
            dr = tanhf(dr); di = tanhf(di); dj = tanhf(dj); dk = tanhf(dk);
            float4 q = cur[tid];
            nxt[tid]      = make_float4(q.x + dr, q.y + di, q.z + dj, q.w + dk);
            nxt[tid + cq] = make_float4(q.x - dr, q.y - di, q.z - dj, q.w - dk);
        }
        __syncthreads();
        float4* t = cur; cur = nxt; nxt = t;
    }
    float4* o4 = (float4*)(g_qA + (size_t)v * QD * 4);
    o4[tid]       = cur[tid];
    o4[tid + 128] = cur[tid + 128];
}

// ---------------- K2: one quaternion layer, 2 tokens/block, packed f32x2 ----------------
__global__ void __launch_bounds__(256) k_layer(int d, int flip) {
    const float* __restrict__ src = flip ? g_qB : g_qA;
    float* __restrict__ dst       = flip ? g_qA : g_qB;
    __shared__ float2 sq[QD][4];
    int tid = threadIdx.x;
    int t0 = blockIdx.x * 2;
    int t1 = t0 + 1; if (t1 > VOCABN - 1) t1 = VOCABN - 1;
    {
        const float4* s0 = (const float4*)(src + (size_t)t0 * QD * 4);
        const float4* s1 = (const float4*)(src + (size_t)t1 * QD * 4);
        float4 a = s0[tid], b = s1[tid];
        sq[tid][0] = make_float2(a.x, b.x);
        sq[tid][1] = make_float2(a.y, b.y);
        sq[tid][2] = make_float2(a.z, b.z);
        sq[tid][3] = make_float2(a.w, b.w);
    }
    __syncthreads();

    ull P[16];
#pragma unroll
    for (int n = 0; n < 16; n++) P[n] = 0ull;

    const float4* wb = g_wT + (size_t)d * QD * QD + tid;
#pragma unroll 4
    for (int i = 0; i < QD; i++) {
        float4 w = __ldg(wb + i * QD);
        ull wr = bcast2(w.x), wi = bcast2(w.y), wj = bcast2(w.z), wk = bcast2(w.w);
        const ull* q = (const ull*)sq[i];
        ull qr = q[0], qi = q[1], qj = q[2], qk = q[3];
        fma2(P[0],  wr, qr); fma2(P[1],  wr, qi); fma2(P[2],  wr, qj); fma2(P[3],  wr, qk);
        fma2(P[4],  wi, qr); fma2(P[5],  wi, qi); fma2(P[6],  wi, qj); fma2(P[7],  wi, qk);
        fma2(P[8],  wj, qr); fma2(P[9],  wj, qi); fma2(P[10], wj, qj); fma2(P[11], wj, qk);
        fma2(P[12], wk, qr); fma2(P[13], wk, qi); fma2(P[14], wk, qj); fma2(P[15], wk, qk);
    }

    float2 F[16];
#pragma unroll
    for (int n = 0; n < 16; n++) F[n] = unpack2(P[n]);

#pragma unroll
    for (int s = 0; s < 2; s++) {
        int t = s ? t1 : t0;
        if (s == 1 && t1 == t0) break;
        // g(n) selects token half
        float p0  = s ? F[0].y  : F[0].x,  p1  = s ? F[1].y  : F[1].x;
        float p2  = s ? F[2].y  : F[2].x,  p3  = s ? F[3].y  : F[3].x;
        float p4  = s ? F[4].y  : F[4].x,  p5  = s ? F[5].y  : F[5].x;
        float p6  = s ? F[6].y  : F[6].x,  p7  = s ? F[7].y  : F[7].x;
        float p8  = s ? F[8].y  : F[8].x,  p9  = s ? F[9].y  : F[9].x;
        float p10 = s ? F[10].y : F[10].x, p11 = s ? F[11].y : F[11].x;
        float p12 = s ? F[12].y : F[12].x, p13 = s ? F[13].y : F[13].x;
        float p14 = s ? F[14].y : F[14].x, p15 = s ? F[15].y : F[15].x;
        // Hamilton combination: P[w*4+a], w in {r,i,j,k}, a = q component
        float dr = p0  - p5  - p10 + 0.f - p15;
        dr = p0 - p5 - p10 - p15;
        float di = p4  + p1  + p14 - p11;
        float dj = p8  - p13 + p2  + p7;
        float dk = p12 + p9  - p6  + p3;
        float norm = sqrtf(dr * dr + di * di + dj * dj + dk * dk);
        float inv = 1.0f / (norm + 1e-8f);
        ((float4*)(dst + (size_t)t * QD * 4))[tid] =
            make_float4(dr * inv, di * inv, dj * inv, dk * inv);
    }
}

// ---------------- K3: per-token stability mean |q_r| ----------------
__global__ void k_L() {
    __shared__ float red[256];
    int v = blockIdx.x, tid = threadIdx.x;
    red[tid] = fabsf(g_qA[((size_t)v * QD + tid) * 4]);
    __syncthreads();
    for (int s = 128; s > 0; s >>= 1) {
        if (tid < s) red[tid] += red[tid + s];
        __syncthreads();
    }
    if (tid == 0) g_L[v] = red[0] * (1.0f / QD);
}

// ---------------- K4: head GEMM on the token table ----------------
__global__ void __launch_bounds__(256) k_head() {
    __shared__ float2 h2[1024];
    int tid = threadIdx.x;
    int t0 = blockIdx.x * 2;
    int t1 = t0 + 1; if (t1 > VOCABN - 1) t1 = VOCABN - 1;
    for (int k = tid; k < 1024; k += 256)
        h2[k] = make_float2(g_qA[(size_t)t0 * 1024 + k], g_qA[(size_t)t1 * 1024 + k]);
    __syncthreads();
    const ull* h = (const ull*)h2;
    for (int j = tid; j < VOCABN; j += 256) {
        ull acc = 0ull;
        const float* w = g_wHT + j;
#pragma unroll 8
        for (int k = 0; k < 1024; k++) {
            fma2(acc, bcast2(__ldg(w + k * VOCABN)), h[k]);
        }
        float2 r = unpack2(acc);
        g_logits[(size_t)t0 * VOCABN + j] = r.x;
        if (t1 != t0) g_logits[(size_t)t1 * VOCABN + j] = r.y;
    }
}

// ---------------- K5: gather logits to output ----------------
__global__ void k_gather(const int* __restrict__ x, float* __restrict__ out) {
    int warp = threadIdx.x >> 5, lane = threadIdx.x & 31;
    int p = blockIdx.x * 8 + warp;
    int tok = x[p];
    const float* row = g_logits + (size_t)tok * VOCABN;
    float* orow = out + (size_t)p * VOCABN;
    for (int v = lane; v < VOCABN; v += 32)
        orow[v] = row[v];
}

// ---------------- K6: stability loss (deterministic single-block reduction) ----------------
__global__ void k_loss(const int* __restrict__ x, float* __restrict__ out, int out_size) {
    __shared__ float red[256];
    int tid = threadIdx.x;
    float s = 0.f;
    for (int p = tid; p < NPOS; p += 256)
        s += g_L[x[p]];
    red[tid] = s;
    __syncthreads();
    for (int k = 128; k > 0; k >>= 1) {
        if (tid < k) red[tid] += red[tid + k];
        __syncthreads();
    }
    if (tid == 0 && out_size > BSV)
        out[BSV] = red[0] * (1.0f / NPOS);
}

// ---------------- launch ----------------
extern "C" void kernel_launch(void* const* d_in, const int* in_sizes, int n_in,
                              void* d_out, int out_size) {
    (void)in_sizes; (void)n_in;
    const int*   x   = (const int*)d_in[0];
    const float* emb = (const float*)d_in[1];
    const float* e0  = (const float*)d_in[2];
    const float* e1  = (const float*)d_in[3];
    const float* e2  = (const float*)d_in[4];
    const float* e3  = (const float*)d_in[5];
    const float* e4  = (const float*)d_in[6];
    const float* e5  = (const float*)d_in[7];
    const float* e6  = (const float*)d_in[8];
    const float* e7  = (const float*)d_in[9];
    const float* wl  = (const float*)d_in[10];
    const float* wh  = (const float*)d_in[11];
    float* out = (float*)d_out;

    k_prep<<<DEPTHN * QD + 1024, 256>>>(wl, wh);
    k_expand<<<VOCABN, 128>>>(emb, e0, e1, e2, e3, e4, e5, e6, e7);
    for (int d = 0; d < DEPTHN; d++)
        k_layer<<<(VOCABN + 1) / 2, 256>>>(d, d & 1);
    k_L<<<VOCABN, 256>>>();
    k_head<<<(VOCABN + 1) / 2, 256>>>();
    k_gather<<<NPOS / 8, 256>>>(x, out);
    k_loss<<<1, 256>>>(x, out, out_size);
}

// round 2
// speedup vs baseline: 1.5208x; 1.5208x over previous
#include <cuda_runtime.h>
#include <cstdint>

#define BATCHN 8
#define SEQN   4096
#define NPOS   (BATCHN*SEQN)
#define VOCABN 257
#define QD     256
#define DEPTHN 6
#define BSV    (NPOS*VOCABN)

typedef unsigned long long ull;
typedef ulonglong2 ull2;

// ---------------- scratch (device globals; no allocations) ----------------
__device__ float4 g_wT[DEPTHN*QD*QD];     // [d][i][o] -> (wr,wi,wj,wk)  (6.3 MB)
__device__ float4 g_wH4[256*VOCABN];      // [k4][j] -> w_head[j][4k4..4k4+3] (1.05 MB)
__device__ float  g_qA[VOCABN*QD*4];      // q table ping (1.05 MB)
__device__ float  g_qB[VOCABN*QD*4];      // q table pong
__device__ float  g_logits[VOCABN*VOCABN];// per-token logits (264 KB)
__device__ float  g_L[VOCABN];            // per-token mean |q_r|

// ---------------- packed f32x2 helpers ----------------
__device__ __forceinline__ ull bcast2(float x) {
    unsigned int u = __float_as_uint(x);
    ull r;
    asm("mov.b64 %0, {%1, %2};" : "=l"(r) : "r"(u), "r"(u));
    return r;
}
__device__ __forceinline__ void fma2(ull& d, ull a, ull b) {
    asm("fma.rn.f32x2 %0, %1, %2, %0;" : "+l"(d) : "l"(a), "l"(b));
}
__device__ __forceinline__ ull add2(ull a, ull b) {
    ull d;
    asm("add.rn.f32x2 %0, %1, %2;" : "=l"(d) : "l"(a), "l"(b));
    return d;
}
__device__ __forceinline__ float2 unpack2(ull v) {
    unsigned int lo, hi;
    asm("mov.b64 {%0, %1}, %2;" : "=r"(lo), "=r"(hi) : "l"(v));
    return make_float2(__uint_as_float(lo), __uint_as_float(hi));
}
#define NEG2 0x8000000080000000ULL

// ---------------- K0a: layer-weight transpose (tiled, coalesced) ----------------
// grid = DEPTHN*8*8 = 384 blocks of 256 threads. Tile 32(i) x 32(o).
__global__ void k_prep_layers(const float* __restrict__ wl) {
    int b = blockIdx.x;
    int d = b >> 6, r = b & 63;
    int it = r >> 3, ot = r & 7;
    __shared__ float4 tile[32][33];
    int tid = threadIdx.x;
    int col = tid & 31, row8 = tid >> 5;
    const float* base = wl + (size_t)d * 4 * QD * QD;
#pragma unroll
    for (int s = 0; s < 4; s++) {
        int oo = row8 + s * 8;
        int o = ot * 32 + oo, i = it * 32 + col;
        float wr = base[0 * QD * QD + o * QD + i];
        float wi = base[1 * QD * QD + o * QD + i];
        float wj = base[2 * QD * QD + o * QD + i];
        float wk = base[3 * QD * QD + o * QD + i];
        tile[oo][col] = make_float4(wr, wi, wj, wk);
    }
    __syncthreads();
#pragma unroll
    for (int s = 0; s < 4; s++) {
        int ii = row8 + s * 8;
        int i = it * 32 + ii, o = ot * 32 + col;
        g_wT[((size_t)d * QD + i) * QD + o] = tile[col][ii];
    }
}

// ---------------- K0b: head-weight retile [j][k] -> [k4][j] ----------------
// grid = 9 (j tiles) * 8 (k4 tiles) = 72 blocks of 256 threads
__global__ void k_prep_head(const float* __restrict__ wh) {
    int b = blockIdx.x;
    int jt = b >> 3, kt = b & 7;
    __shared__ float4 tile[32][33];
    int tid = threadIdx.x;
    int col = tid & 31, row8 = tid >> 5;
#pragma unroll
    for (int s = 0; s < 4; s++) {
        int jj = row8 + s * 8;
        int j = jt * 32 + jj, k4 = kt * 32 + col;
        if (j < VOCABN)
            tile[jj][col] = *(const float4*)(wh + (size_t)j * 1024 + k4 * 4);
    }
    __syncthreads();
#pragma unroll
    for (int s = 0; s < 4; s++) {
        int kk = row8 + s * 8;
        int k4 = kt * 32 + kk, j = jt * 32 + col;
        if (j < VOCABN)
            g_wH4[(size_t)k4 * VOCABN + j] = tile[col][kk];
    }
}

// ---------------- K1: expansion stages (cq 1 -> 256), one block per vocab token ----------------
__global__ void k_expand(const float* __restrict__ emb,
                         const float* __restrict__ e0, const float* __restrict__ e1,
                         const float* __restrict__ e2, const float* __restrict__ e3,
                         const float* __restrict__ e4, const float* __restrict__ e5,
                         const float* __restrict__ e6, const float* __restrict__ e7) {
    __shared__ float4 bufA[QD];
    __shared__ float4 bufB[QD];
    int v = blockIdx.x, tid = threadIdx.x;
    if (tid == 0)
        bufA[0] = make_float4(emb[v * 4 + 0], emb[v * 4 + 1], emb[v * 4 + 2], emb[v * 4 + 3]);
    __syncthreads();
    const float* ws[8] = {e0, e1, e2, e3, e4, e5, e6, e7};
    float4* cur = bufA;
    float4* nxt = bufB;
    for (int s = 0; s < 8; s++) {
        int cq = 1 << s;
        if (tid < cq) {
            const float* W = ws[s];
            int cq2 = cq * cq;
            float dr = 0.f, di = 0.f, dj = 0.f, dk = 0.f;
            for (int i = 0; i < cq; i++) {
                float4 q = cur[i];
                float wr = W[tid * cq + i];
                float wi = W[cq2 + tid * cq + i];
                float wj = W[2 * cq2 + tid * cq + i];
                float wk = W[3 * cq2 + tid * cq + i];
                dr += wr * q.x - wi * q.y - wj * q.z - wk * q.w;
                di += wi * q.x + wr * q.y + wk * q.z - wj * q.w;
                dj += wj * q.x - wk * q.y + wr * q.z + wi * q.w;
                dk += wk * q.x + wj * q.y - wi * q.z + wr * q.w;
            }
            dr = tanhf(dr); di = tanhf(di); dj = tanhf(dj); dk = tanhf(dk);
            float4 q = cur[tid];
            nxt[tid]      = make_float4(q.x + dr, q.y + di, q.z + dj, q.w + dk);
            nxt[tid + cq] = make_float4(q.x - dr, q.y - di, q.z - dj, q.w - dk);
        }
        __syncthreads();
        float4* t = cur; cur = nxt; nxt = t;
    }
    float4* o4 = (float4*)(g_qA + (size_t)v * QD * 4);
    o4[tid]       = cur[tid];
    o4[tid + 128] = cur[tid + 128];
}

// ---------------- K2: one quaternion layer; 2 tokens/block, 1024 thr, 4-way K-split ----------------
__global__ void __launch_bounds__(1024, 1) k_layer(int d, int flip) {
    const float* __restrict__ src = flip ? g_qB : g_qA;
    float* __restrict__ dst       = flip ? g_qA : g_qB;
    __shared__ ull sq[QD][4];      // token-pair packed q components (8 KB)
    __shared__ ull red[4][768];    // K-split partials (24 KB)
    int tid = threadIdx.x;
    int o = tid & 255, p = tid >> 8;
    int t0 = blockIdx.x * 2;
    int t1 = t0 + 1; if (t1 > VOCABN - 1) t1 = VOCABN - 1;

    if (tid < 512) {
        int half = tid >> 8;
        int oo = tid & 255;
        int t = half ? t1 : t0;
        float4 a = ((const float4*)(src + (size_t)t * 1024))[oo];
        ((float*)&sq[oo][0])[half] = a.x;
        ((float*)&sq[oo][1])[half] = a.y;
        ((float*)&sq[oo][2])[half] = a.z;
        ((float*)&sq[oo][3])[half] = a.w;
    }
    __syncthreads();

    ull P[16];
#pragma unroll
    for (int n = 0; n < 16; n++) P[n] = 0ull;

    const float4* wb = g_wT + ((size_t)d * QD + p * 64) * QD + o;
    const ull* qbase = &sq[p * 64][0];
#pragma unroll 4
    for (int n = 0; n < 64; n++) {
        float4 w = __ldg(wb + (size_t)n * QD);
        ull wr = bcast2(w.x), wi = bcast2(w.y), wj = bcast2(w.z), wk = bcast2(w.w);
        ull2 qa = *(const ull2*)(qbase + 4 * n);
        ull2 qb = *(const ull2*)(qbase + 4 * n + 2);
        ull qr = qa.x, qi = qa.y, qj = qb.x, qk = qb.y;
        fma2(P[0],  wr, qr); fma2(P[1],  wr, qi); fma2(P[2],  wr, qj); fma2(P[3],  wr, qk);
        fma2(P[4],  wi, qr); fma2(P[5],  wi, qi); fma2(P[6],  wi, qj); fma2(P[7],  wi, qk);
        fma2(P[8],  wj, qr); fma2(P[9],  wj, qi); fma2(P[10], wj, qj); fma2(P[11], wj, qk);
        fma2(P[12], wk, qr); fma2(P[13], wk, qi); fma2(P[14], wk, qj); fma2(P[15], wk, qk);
    }

    // Hamilton combine (packed over the token pair)
    ull dr = add2(add2(P[0],  P[5]  ^ NEG2), add2(P[10] ^ NEG2, P[15] ^ NEG2));
    ull di = add2(add2(P[4],  P[1]),         add2(P[14],        P[11] ^ NEG2));
    ull dj = add2(add2(P[8],  P[13] ^ NEG2), add2(P[2],         P[7]));
    ull dk = add2(add2(P[12], P[9]),         add2(P[6]  ^ NEG2, P[3]));

    if (p) {
        int idx = (p - 1) * 256 + o;
        red[0][idx] = dr; red[1][idx] = di; red[2][idx] = dj; red[3][idx] = dk;
    }
    __syncthreads();
    if (p == 0) {
#pragma unroll
        for (int s = 0; s < 3; s++) {
            dr = add2(dr, red[0][s * 256 + o]);
            di = add2(di, red[1][s * 256 + o]);
            dj = add2(dj, red[2][s * 256 + o]);
            dk = add2(dk, red[3][s * 256 + o]);
        }
        float2 R = unpack2(dr), I = unpack2(di), J = unpack2(dj), K = unpack2(dk);
        float n0 = sqrtf(R.x * R.x + I.x * I.x + J.x * J.x + K.x * K.x);
        float v0 = 1.0f / (n0 + 1e-8f);
        ((float4*)(dst + (size_t)t0 * 1024))[o] =
            make_float4(R.x * v0, I.x * v0, J.x * v0, K.x * v0);
        float n1 = sqrtf(R.y * R.y + I.y * I.y + J.y * J.y + K.y * K.y);
        float v1 = 1.0f / (n1 + 1e-8f);
        ((float4*)(dst + (size_t)t1 * 1024))[o] =
            make_float4(R.y * v1, I.y * v1, J.y * v1, K.y * v1);
    }
}

// ---------------- K3: per-token stability mean |q_r| ----------------
__global__ void k_L() {
    __shared__ float red[256];
    int v = blockIdx.x, tid = threadIdx.x;
    red[tid] = fabsf(g_qA[((size_t)v * QD + tid) * 4]);
    __syncthreads();
    for (int s = 128; s > 0; s >>= 1) {
        if (tid < s) red[tid] += red[tid + s];
        __syncthreads();
    }
    if (tid == 0) g_L[v] = red[0] * (1.0f / QD);
}

// ---------------- K4: head GEMM; 2 tokens/block, 1024 thr, 4-way K-split ----------------
__global__ void __launch_bounds__(1024, 1) k_head() {
    __shared__ ull hq[2][512];     // (q_k, q_{k+1}) pairs per token (8 KB)
    __shared__ ull redh[2][768];   // K-split partials (12 KB)
    __shared__ float redj[2][32];  // j=256 column partials
    int tid = threadIdx.x;
    int j = tid & 255, p = tid >> 8;
    int t0 = blockIdx.x * 2;
    int t1 = t0 + 1; if (t1 > VOCABN - 1) t1 = VOCABN - 1;

    {
        int half = tid >> 9;
        int idx = tid & 511;
        int t = half ? t1 : t0;
        hq[half][idx] = ((const ull*)(g_qA + (size_t)t * 1024))[idx];
    }
    __syncthreads();

    ull a0 = 0ull, a1 = 0ull;
    const float4* wb = g_wH4 + (size_t)(p * 64) * VOCABN + j;
    const ull* q0 = &hq[0][p * 128];
    const ull* q1 = &hq[1][p * 128];
#pragma unroll 4
    for (int n = 0; n < 64; n++) {
        float4 w = __ldg(wb + (size_t)n * VOCABN);
        ull w01 = *(const ull*)&w.x;
        ull w23 = *(const ull*)&w.z;
        ull2 qa = *(const ull2*)(q0 + 2 * n);
        ull2 qb = *(const ull2*)(q1 + 2 * n);
        fma2(a0, w01, qa.x); fma2(a0, w23, qa.y);
        fma2(a1, w01, qb.x); fma2(a1, w23, qb.y);
    }
    if (p) {
        redh[0][(p - 1) * 256 + j] = a0;
        redh[1][(p - 1) * 256 + j] = a1;
    }

    // j == 256 column: 1024-way K split, k = tid
    {
        float w256 = ((const float*)&g_wH4[(size_t)(tid >> 2) * VOCABN + 256])[tid & 3];
        float s0 = w256 * ((const float*)hq[0])[tid];
        float s1 = w256 * ((const float*)hq[1])[tid];
#pragma unroll
        for (int off = 16; off; off >>= 1) {
            s0 += __shfl_down_sync(0xFFFFFFFFu, s0, off);
            s1 += __shfl_down_sync(0xFFFFFFFFu, s1, off);
        }
        if ((tid & 31) == 0) {
            redj[0][tid >> 5] = s0;
            redj[1][tid >> 5] = s1;
        }
    }
    __syncthreads();

    if (p == 0) {
#pragma unroll
        for (int s = 0; s < 3; s++) {
            a0 = add2(a0, redh[0][s * 256 + j]);
            a1 = add2(a1, redh[1][s * 256 + j]);
        }
        float2 r0 = unpack2(a0), r1 = unpack2(a1);
        g_logits[(size_t)t0 * VOCABN + j] = r0.x + r0.y;
        g_logits[(size_t)t1 * VOCABN + j] = r1.x + r1.y;
    }
    if (tid == 0) {
        float s0 = 0.f, s1 = 0.f;
#pragma unroll
        for (int w = 0; w < 32; w++) { s0 += redj[0][w]; s1 += redj[1][w]; }
        g_logits[(size_t)t0 * VOCABN + 256] = s0;
        g_logits[(size_t)t1 * VOCABN + 256] = s1;
    }
}

// ---------------- K5: gather logits to output ----------------
__global__ void k_gather(const int* __restrict__ x, float* __restrict__ out) {
    int warp = threadIdx.x >> 5, lane = threadIdx.x & 31;
    int pp = blockIdx.x * 8 + warp;
    int tok = x[pp];
    const float* row = g_logits + (size_t)tok * VOCABN;
    float* orow = out + (size_t)pp * VOCABN;
    for (int v = lane; v < VOCABN; v += 32)
        orow[v] = row[v];
}

// ---------------- K6: stability loss ----------------
__global__ void k_loss(const int* __restrict__ x, float* __restrict__ out, int out_size) {
    __shared__ float red[1024];
    int tid = threadIdx.x;
    float s = 0.f;
    for (int pth = tid; pth < NPOS; pth += 1024)
        s += g_L[x[pth]];
    red[tid] = s;
    __syncthreads();
    for (int k = 512; k > 0; k >>= 1) {
        if (tid < k) red[tid] += red[tid + k];
        __syncthreads();
    }
    if (tid == 0 && out_size > BSV)
        out[BSV] = red[0] * (1.0f / NPOS);
}

// ---------------- launch ----------------
extern "C" void kernel_launch(void* const* d_in, const int* in_sizes, int n_in,
                              void* d_out, int out_size) {
    (void)in_sizes; (void)n_in;
    const int*   x   = (const int*)d_in[0];
    const float* emb = (const float*)d_in[1];
    const float* e0  = (const float*)d_in[2];
    const float* e1  = (const float*)d_in[3];
    const float* e2  = (const float*)d_in[4];
    const float* e3  = (const float*)d_in[5];
    const float* e4  = (const float*)d_in[6];
    const float* e5  = (const float*)d_in[7];
    const float* e6  = (const float*)d_in[8];
    const float* e7  = (const float*)d_in[9];
    const float* wl  = (const float*)d_in[10];
    const float* wh  = (const float*)d_in[11];
    float* out = (float*)d_out;

    k_prep_layers<<<DEPTHN * 64, 256>>>(wl);
    k_prep_head<<<72, 256>>>(wh);
    k_expand<<<VOCABN, 128>>>(emb, e0, e1, e2, e3, e4, e5, e6, e7);
    for (int d = 0; d < DEPTHN; d++)
        k_layer<<<(VOCABN + 1) / 2, 1024>>>(d, d & 1);
    k_L<<<VOCABN, 256>>>();
    k_head<<<(VOCABN + 1) / 2, 1024>>>();
    k_gather<<<NPOS / 8, 256>>>(x, out);
    k_loss<<<1, 1024>>>(x, out, out_size);
}